// round 8
// baseline (speedup 1.0000x reference)
#include <cuda_runtime.h>

// Locally-connected 2D: out[oy,ox] = sum_{ky,kx} x[oy+ky, ox+kx] * W[oy,ox,ky,kx]
// x: [450,450] f32, W: [436,436,15,15] f32 (171 MB streamed once), out: [436,436].
// Warp per PIXEL QUAD: W block of 4 consecutive pixels = 900 floats = 3600 B,
// 16B-aligned -> 7x LDG.128 + tail. x offsets from a per-block int4 smem table
// (no divisions in hot path). 4 accumulators; straddling unroll steps use
// predicated FMAs. L2 prefetch ~96 px ahead. __ldcs keeps W evict-first.

#define IN_H 450
#define IN_W 450
#define KH 15
#define KW 15
#define OH 436
#define OW 436
#define KSIZE 225
#define NPIX (OH * OW)       // 190096
#define NQUAD (NPIX / 4)     // 47524 (OW % 4 == 0 -> quads never cross rows)
#define PFQ 24               // prefetch distance in quads (96 pixels, ~86 KB)

__global__ __launch_bounds__(256)
void lc2d_kernel(const float* __restrict__ x,
                 const float* __restrict__ W,
                 float* __restrict__ out)
{
    // xoff4[f], f in [0,900): pix = f/225, k = f%225,
    // offset = (k/15)*IN_W + k%15 + pix   (pix shifts the patch right by 1).
    __shared__ int xoff4[900];
    for (int f = threadIdx.x; f < 900; f += 256) {
        const int pix = f / KSIZE;
        const int k   = f - KSIZE * pix;
        const int ky  = k / KW;
        xoff4[f] = ky * IN_W + (k - ky * KW) + pix;
    }
    __syncthreads();

    const int lane = threadIdx.x & 31;
    const int quad = (blockIdx.x * blockDim.x + threadIdx.x) >> 5;
    if (quad >= NQUAD) return;

    const int pix0 = quad * 4;
    const int oy = pix0 / OW;
    const int ox = pix0 - oy * OW;

    const float4* W4 = (const float4*)(W + (size_t)quad * 900) + lane;
    const int4*   ot = (const int4*)xoff4 + lane;
    const float*  xb = x + oy * IN_W + ox;

    // L2 prefetch: 29 lanes cover the 3600B W block PFQ quads ahead.
    if (lane < 29 && quad + PFQ < NQUAD) {
        const char* pf = (const char*)(W + (size_t)(quad + PFQ) * 900) + lane * 128;
        asm volatile("prefetch.global.L2 [%0];" :: "l"(pf));
    }

    float a0 = 0.0f, a1 = 0.0f, a2 = 0.0f, a3 = 0.0f;

    // Clean step: all 4 elements belong to pixel ACC.
#define STEP_CLEAN(i, ACC)                                                \
    {                                                                     \
        const float4 w = __ldcs(W4 + 32 * (i));                           \
        const int4   o = ot[32 * (i)];                                    \
        ACC = fmaf(w.x, __ldg(xb + o.x), ACC);                            \
        ACC = fmaf(w.y, __ldg(xb + o.y), ACC);                            \
        ACC = fmaf(w.z, __ldg(xb + o.z), ACC);                            \
        ACC = fmaf(w.w, __ldg(xb + o.w), ACC);                            \
    }

    // Straddle step: elements split between A_LO (f < B) and A_HI (f >= B).
#define STEP_SPLIT(i, B, A_LO, A_HI)                                      \
    {                                                                     \
        const float4 w = __ldcs(W4 + 32 * (i));                           \
        const int4   o = ot[32 * (i)];                                    \
        const int f0 = (lane << 2) + ((i) << 7);                          \
        const float v0 = __ldg(xb + o.x);                                 \
        const float v1 = __ldg(xb + o.y);                                 \
        const float v2 = __ldg(xb + o.z);                                 \
        const float v3 = __ldg(xb + o.w);                                 \
        if (f0     < (B)) A_LO = fmaf(w.x, v0, A_LO); else A_HI = fmaf(w.x, v0, A_HI); \
        if (f0 + 1 < (B)) A_LO = fmaf(w.y, v1, A_LO); else A_HI = fmaf(w.y, v1, A_HI); \
        if (f0 + 2 < (B)) A_LO = fmaf(w.z, v2, A_LO); else A_HI = fmaf(w.z, v2, A_HI); \
        if (f0 + 3 < (B)) A_LO = fmaf(w.w, v3, A_LO); else A_HI = fmaf(w.w, v3, A_HI); \
    }

    STEP_CLEAN(0, a0)            // f   0..127  -> pixel 0
    STEP_SPLIT(1, 225, a0, a1)   // f 128..255  -> pixels 0/1
    STEP_CLEAN(2, a1)            // f 256..383  -> pixel 1
    STEP_SPLIT(3, 450, a1, a2)   // f 384..511  -> pixels 1/2
    STEP_CLEAN(4, a2)            // f 512..639  -> pixel 2
    STEP_SPLIT(5, 675, a2, a3)   // f 640..767  -> pixels 2/3
    STEP_CLEAN(6, a3)            // f 768..895  -> pixel 3

    // Tail: f = 896..899 (pixel 3, k = 221..224), lane 0 only.
    if (lane == 0) {
        const float4 w = __ldcs(W4 + 224);          // W4 already +lane (=0)
        const int4   o = ((const int4*)xoff4)[224];
        a3 = fmaf(w.x, __ldg(xb + o.x), a3);
        a3 = fmaf(w.y, __ldg(xb + o.y), a3);
        a3 = fmaf(w.z, __ldg(xb + o.z), a3);
        a3 = fmaf(w.w, __ldg(xb + o.w), a3);
    }

    // Four interleaved warp reductions (independent chains -> ILP).
#pragma unroll
    for (int off = 16; off > 0; off >>= 1) {
        a0 += __shfl_down_sync(0xffffffffu, a0, off);
        a1 += __shfl_down_sync(0xffffffffu, a1, off);
        a2 += __shfl_down_sync(0xffffffffu, a2, off);
        a3 += __shfl_down_sync(0xffffffffu, a3, off);
    }

    if (lane == 0) {
        float4 r;
        r.x = a0; r.y = a1; r.z = a2; r.w = a3;
        *(float4*)(out + pix0) = r;                 // 16B-aligned STG.128
    }

#undef STEP_CLEAN
#undef STEP_SPLIT
}

extern "C" void kernel_launch(void* const* d_in, const int* in_sizes, int n_in,
                              void* d_out, int out_size)
{
    const float* x = (const float*)d_in[0];
    const float* W = (const float*)d_in[1];
    float* out = (float*)d_out;

    const int threads = 256;                    // 8 warps = 8 quads = 32 px/block
    const int blocks = (NQUAD + 7) / 8;         // 5941
    lc2d_kernel<<<blocks, threads>>>(x, W, out);
}

// round 9
// speedup vs baseline: 1.0420x; 1.0420x over previous
#include <cuda_runtime.h>

// Locally-connected 2D: out[oy,ox] = sum_{ky,kx} x[oy+ky, ox+kx] * W[oy,ox,ky,kx]
// x: [450,450] f32, W: [436,436,15,15] f32 (171 MB streamed once), out: [436,436].
// Warp per PIXEL PAIR (best measured shape) + LONG-RANGE L2 prefetch:
// the consumption rate is ~5 px/ns chip-wide, so a useful prefetch must lead
// demand by >~600ns ~= 3000 pixels (previous 96-px lead arrived ~19ns early,
// inside DRAM latency -> useless). At +1536 pairs the prefetch stream pulls W
// into L2 ahead of demand; demand __ldcs then hits L2 instead of the
// DRAM-miss path. In-flight window ~2.7 MB << 126 MB L2.

#define IN_H 450
#define IN_W 450
#define KH 15
#define KW 15
#define OH 436
#define OW 436
#define KSIZE 225
#define NPIX (OH * OW)       // 190096
#define NPAIR (NPIX / 2)     // 95048
#define PFP 1536             // prefetch distance in pairs (3072 px, ~2.7 MB lead)

__global__ __launch_bounds__(256)
void lc2d_kernel(const float* __restrict__ x,
                 const float* __restrict__ W,
                 float* __restrict__ out)
{
    // Offset table for both pixels of a pair: f in [0,450),
    // k = f mod 225, pixel = f / 225; xoff2[f] = (k/15)*IN_W + k%15 + pixel.
    __shared__ int xoff2[450];
    for (int f = threadIdx.x; f < 450; f += 256) {
        const int pp = (f >= KSIZE) ? 1 : 0;
        const int k  = f - KSIZE * pp;
        const int ky = k / KW;
        xoff2[f] = ky * IN_W + (k - ky * KW) + pp;
    }
    __syncthreads();

    const int lane = threadIdx.x & 31;
    const int pair = (blockIdx.x * blockDim.x + threadIdx.x) >> 5;
    if (pair >= NPAIR) return;

    const int pix0 = pair * 2;
    const int oy = pix0 / OW;
    const int ox = pix0 - oy * OW;            // pair never crosses a row (OW even)

    const float2* W2 = (const float2*)(W + (size_t)pair * 450) + lane;
    const float*  xb = x + oy * IN_W + ox;
    const int2*   ot = (const int2*)xoff2 + lane;

    // Long-range L2 prefetch: 15 lanes x 128B cover the 1800B W block of the
    // pair PFP ahead (each pair prefetched exactly once, ~600ns before demand).
    if (lane < 15 && pair + PFP < NPAIR) {
        const char* pf = (const char*)(W + (size_t)(pair + PFP) * 450) + lane * 128;
        asm volatile("prefetch.global.L2 [%0];" :: "l"(pf));
    }

    float acc0 = 0.0f, acc1 = 0.0f;

    // i = 0..2 : f = 2*(lane+32i)+{0,1} <= 191  -> all pixel 0
#pragma unroll
    for (int i = 0; i < 3; i++) {
        const float2 w = __ldcs(W2 + 32 * i);
        const int2   o = ot[32 * i];
        acc0 = fmaf(w.x, __ldg(xb + o.x), acc0);
        acc0 = fmaf(w.y, __ldg(xb + o.y), acc0);
    }
    // i = 3 : straddles f = 225 (lane-dependent routing)
    {
        const float2 w = __ldcs(W2 + 96);
        const int2   o = ot[96];
        const float xa = __ldg(xb + o.x);
        const float xv = __ldg(xb + o.y);
        if (lane <= 16) acc0 = fmaf(w.x, xa, acc0);
        else            acc1 = fmaf(w.x, xa, acc1);
        if (lane <= 15) acc0 = fmaf(w.y, xv, acc0);
        else            acc1 = fmaf(w.y, xv, acc1);
    }
    // i = 4..6 : f >= 256 -> all pixel 1
#pragma unroll
    for (int i = 4; i < 7; i++) {
        const float2 w = __ldcs(W2 + 32 * i);
        const int2   o = ot[32 * i];
        acc1 = fmaf(w.x, __ldg(xb + o.x), acc1);
        acc1 = fmaf(w.y, __ldg(xb + o.y), acc1);
    }
    // tail: f = 448,449 -> pixel 1 (k = 223,224), lane 0 only
    if (lane == 0) {
        const float2 w = __ldcs(W2 + 224);          // W2 already +lane (=0)
        const int2   o = ((const int2*)xoff2)[224];
        acc1 = fmaf(w.x, __ldg(xb + o.x), acc1);
        acc1 = fmaf(w.y, __ldg(xb + o.y), acc1);
    }

    // Two interleaved warp reductions (independent chains -> ILP)
#pragma unroll
    for (int off = 16; off > 0; off >>= 1) {
        acc0 += __shfl_down_sync(0xffffffffu, acc0, off);
        acc1 += __shfl_down_sync(0xffffffffu, acc1, off);
    }

    if (lane == 0) {
        out[pix0]     = acc0;
        out[pix0 + 1] = acc1;
    }
}

extern "C" void kernel_launch(void* const* d_in, const int* in_sizes, int n_in,
                              void* d_out, int out_size)
{
    const float* x = (const float*)d_in[0];
    const float* W = (const float*)d_in[1];
    float* out = (float*)d_out;

    const int threads = 256;                    // 8 warps = 8 pairs = 16 px/block
    const int blocks = (NPAIR + 7) / 8;         // 11881 (exact)
    lc2d_kernel<<<blocks, threads>>>(x, W, out);
}

// round 10
// speedup vs baseline: 1.0600x; 1.0173x over previous
#include <cuda_runtime.h>

// Locally-connected 2D: out[oy,ox] = sum_{ky,kx} x[oy+ky, ox+kx] * W[oy,ox,ky,kx]
// x: [450,450] f32, W: [436,436,15,15] f32 (171 MB streamed once), out: [436,436].
//
// Consolidated best-of: warp-per-pixel with SCALAR LDG.32 W loads (empirically
// the highest-BW shape: 4.79 TB/s vs 4.56 for LDG.64, 4.39 for LDG.128) with
// the per-pixel address math replaced by a per-block smem offset table
// (removes the 7 div-by-15 chains that put R5 at issue=77%). Dual
// accumulators, batched independent loads, __ldcs streaming, short L2
// prefetch. This targets the measured ~4.8 TB/s demand-read ceiling; floor
// at that BW is ~36 us.

#define IN_H 450
#define IN_W 450
#define KH 15
#define KW 15
#define OH 436
#define OW 436
#define KSIZE 225
#define NPIX (OH * OW)     // 190096
#define PFD 96             // prefetch distance in pixels

__global__ __launch_bounds__(256)
void lc2d_kernel(const float* __restrict__ x,
                 const float* __restrict__ W,
                 float* __restrict__ out)
{
    // xoff[k] = (k/15)*IN_W + k%15 for k in [0,225). Built once per block.
    __shared__ int xoff[KSIZE];
    for (int k = threadIdx.x; k < KSIZE; k += 256) {
        const int ky = k / KW;
        xoff[k] = ky * IN_W + (k - ky * KW);
    }
    __syncthreads();

    const int lane = threadIdx.x & 31;
    const int pix  = (blockIdx.x * blockDim.x + threadIdx.x) >> 5;
    if (pix >= NPIX) return;

    const int oy = pix / OW;
    const int ox = pix - oy * OW;

    const float* wp = W + (size_t)pix * KSIZE + lane;
    const float* xb = x + oy * IN_W + ox;

    // L2 prefetch: 8 lanes x 128B cover the 900B W block PFD pixels ahead.
    if (lane < 8 && pix + PFD < NPIX) {
        const char* pf = (const char*)(W + (size_t)(pix + PFD) * KSIZE) + lane * 128;
        asm volatile("prefetch.global.L2 [%0];" :: "l"(pf));
    }

    // Per-lane x offsets from the table: conflict-free LDS (stride 32).
    const int o0 = xoff[lane];
    const int o1 = xoff[lane + 32];
    const int o2 = xoff[lane + 64];
    const int o3 = xoff[lane + 96];
    const int o4 = xoff[lane + 128];
    const int o5 = xoff[lane + 160];
    const int o6 = xoff[lane + 192];

    // Batch all W loads (independent -> max MLP), then x loads, then FMAs.
    const float w0 = __ldcs(wp);
    const float w1 = __ldcs(wp + 32);
    const float w2 = __ldcs(wp + 64);
    const float w3 = __ldcs(wp + 96);
    const float w4 = __ldcs(wp + 128);
    const float w5 = __ldcs(wp + 160);
    const float w6 = __ldcs(wp + 192);

    const float v0 = __ldg(xb + o0);
    const float v1 = __ldg(xb + o1);
    const float v2 = __ldg(xb + o2);
    const float v3 = __ldg(xb + o3);
    const float v4 = __ldg(xb + o4);
    const float v5 = __ldg(xb + o5);
    const float v6 = __ldg(xb + o6);

    float s0 = w0 * v0;
    float s1 = w1 * v1;
    s0 = fmaf(w2, v2, s0);
    s1 = fmaf(w3, v3, s1);
    s0 = fmaf(w4, v4, s0);
    s1 = fmaf(w5, v5, s1);
    s0 = fmaf(w6, v6, s0);

    // Tail element k = 224 (ky=14, kx=14): lane 0 only.
    if (lane == 0)
        s1 = fmaf(__ldcs(wp + 224), __ldg(xb + 14 * IN_W + 14), s1);

    float sum = s0 + s1;
#pragma unroll
    for (int off = 16; off > 0; off >>= 1)
        sum += __shfl_down_sync(0xffffffffu, sum, off);

    if (lane == 0)
        out[pix] = sum;
}

extern "C" void kernel_launch(void* const* d_in, const int* in_sizes, int n_in,
                              void* d_out, int out_size)
{
    const float* x = (const float*)d_in[0];
    const float* W = (const float*)d_in[1];
    float* out = (float*)d_out;

    const int threads = 256;               // 8 warps = 8 pixels per block
    const int blocks = (NPIX + 7) / 8;     // 23762
    lc2d_kernel<<<blocks, threads>>>(x, W, out);
}